// round 1
// baseline (speedup 1.0000x reference)
#include <cuda_runtime.h>
#include <math.h>

#define NN   8192
#define SQ   4
#define DIM  512
#define NH   4
#define DH   128
#define ET   73728
#define BOUT 128

// ---------------- scratch (device globals; no runtime alloc allowed) -------
__device__ float g_node_raw[NN * 8];
__device__ float g_node_pos[NN * DIM];
__device__ float g_x [NN * DIM];
__device__ float g_xn[NN * DIM];
__device__ float g_Q [NN * DIM];
__device__ float g_K [NN * DIM];
__device__ float g_V [NN * DIM];
__device__ float g_eA[ET * DIM];        // edge hidden -> e1
__device__ float g_eB[ET * DIM];        // e0
__device__ float g_Ew1[ET * 2 * DIM];   // layer-0 Ew/Eb (position-invariant)
__device__ float g_Ew2[ET * 2 * DIM];   // layer-1 Ew/Eb (per position)
__device__ float g_logits[ET * NH];
__device__ float g_m[NN * NH];
__device__ float g_z[NN * NH];

// ---------------- small utility kernels ------------------------------------
__global__ void kzero(float* __restrict__ p, int n) {
    int i = blockIdx.x * blockDim.x + threadIdx.x;
    if (i < n) p[i] = 0.f;
}

__global__ void k_selfloop(const int* __restrict__ ei, const float* __restrict__ emb) {
    int e = blockIdx.x * blockDim.x + threadIdx.x;
    if (e >= ET) return;
    int s = ei[e], d = ei[ET + e];
    if (s == d) {
        #pragma unroll
        for (int r = 0; r < 8; r++)
            atomicAdd(&g_node_raw[s * 8 + r], emb[e * 8 + r]);
    }
}

// out[n,j] = relu( sum_r in[n,r]*w1[r,j] + b1[j] ), in is rows x 8
__global__ void k_mlp1(const float* __restrict__ in, const float* __restrict__ w1,
                       const float* __restrict__ b1, float* __restrict__ out, int rows) {
    long long idx = (long long)blockIdx.x * blockDim.x + threadIdx.x;
    if (idx >= (long long)rows * DIM) return;
    int n = (int)(idx >> 9), j = (int)(idx & 511);
    const float* ip = in + (long long)n * 8;
    float acc = b1[j];
    #pragma unroll
    for (int r = 0; r < 8; r++) acc = fmaf(ip[r], w1[r * DIM + j], acc);
    out[idx] = fmaxf(acc, 0.f);
}

// x[n,j] = query[n, s, j] + node_pos[n,j]
__global__ void k_add(const float* __restrict__ query, const float* __restrict__ npos,
                      float* __restrict__ x, int s) {
    int idx = blockIdx.x * blockDim.x + threadIdx.x;
    if (idx >= NN * DIM) return;
    int n = idx >> 9, j = idx & 511;
    x[idx] = query[(long long)n * SQ * DIM + (long long)s * DIM + j] + npos[idx];
}

__global__ void k_gather(const float* __restrict__ x, const int* __restrict__ mapping,
                         float* __restrict__ out, int s) {
    int idx = blockIdx.x * blockDim.x + threadIdx.x;
    if (idx >= BOUT * DIM) return;
    int b = idx >> 9, j = idx & 511;
    out[(long long)b * SQ * DIM + (long long)s * DIM + j] =
        x[(long long)mapping[b] * DIM + j];
}

// ---------------- SGEMM: C[M,N] = A[M,K] @ B[K,N] (+bias). All row-major. --
__global__ void __launch_bounds__(256)
sgemm(const float* __restrict__ A, const float* __restrict__ Bw,
      const float* __restrict__ bias, float* __restrict__ C,
      int M, int N, int K) {
    __shared__ __align__(16) float As[8][128];
    __shared__ __align__(16) float Bs[8][128];
    const int tid  = threadIdx.x;
    const int brow = blockIdx.y * 128;
    const int bcol = blockIdx.x * 128;
    const int trow = (tid >> 4) * 8;
    const int tcol = (tid & 15) * 8;

    const int arow = tid >> 1, acol = (tid & 1) * 4;
    const int brw  = tid >> 5, bcl  = (tid & 31) * 4;
    const float* Ap = A  + (long long)(brow + arow) * K + acol;
    const float* Bp = Bw + (long long)brw * N + bcol + bcl;

    float acc[8][8];
    #pragma unroll
    for (int i = 0; i < 8; i++)
        #pragma unroll
        for (int j = 0; j < 8; j++) acc[i][j] = 0.f;

    for (int k0 = 0; k0 < K; k0 += 8) {
        float4 av = *(const float4*)(Ap + k0);
        As[acol + 0][arow] = av.x;
        As[acol + 1][arow] = av.y;
        As[acol + 2][arow] = av.z;
        As[acol + 3][arow] = av.w;
        float4 bv = *(const float4*)(Bp + (long long)k0 * N);
        *(float4*)&Bs[brw][bcl] = bv;
        __syncthreads();
        #pragma unroll
        for (int kk = 0; kk < 8; kk++) {
            float a[8], b[8];
            #pragma unroll
            for (int i = 0; i < 8; i++) a[i] = As[kk][trow + i];
            #pragma unroll
            for (int j = 0; j < 8; j++) b[j] = Bs[kk][tcol + j];
            #pragma unroll
            for (int i = 0; i < 8; i++)
                #pragma unroll
                for (int j = 0; j < 8; j++) acc[i][j] = fmaf(a[i], b[j], acc[i][j]);
        }
        __syncthreads();
    }

    #pragma unroll
    for (int i = 0; i < 8; i++) {
        float* cp = C + (long long)(brow + trow + i) * N + bcol + tcol;
        #pragma unroll
        for (int j = 0; j < 8; j += 4) {
            float4 v;
            v.x = acc[i][j + 0] + (bias ? bias[bcol + tcol + j + 0] : 0.f);
            v.y = acc[i][j + 1] + (bias ? bias[bcol + tcol + j + 1] : 0.f);
            v.z = acc[i][j + 2] + (bias ? bias[bcol + tcol + j + 2] : 0.f);
            v.w = acc[i][j + 3] + (bias ? bias[bcol + tcol + j + 3] : 0.f);
            *(float4*)(cp + j) = v;
        }
    }
}

// ---------------- edge attention: s, e_out, per-(e,h) logits ---------------
__global__ void k_edge(const float* __restrict__ Qb, const float* __restrict__ Kb,
                       const int* __restrict__ src, const int* __restrict__ dst,
                       const float* __restrict__ EwEb, const float* __restrict__ aw,
                       float* __restrict__ e_out) {
    int w = (blockIdx.x * blockDim.x + threadIdx.x) >> 5;
    int lane = threadIdx.x & 31;
    if (w >= ET * NH) return;
    int e = w >> 2, h = w & 3;
    int sn = src[e], dn = dst[e];
    const float* qp  = Qb   + (long long)dn * DIM + h * DH;
    const float* kp  = Kb   + (long long)sn * DIM + h * DH;
    const float* ewp = EwEb + (long long)e * (2 * DIM) + h * 256;
    float lg = 0.f;
    float vals[4];
    #pragma unroll
    for (int i = 0; i < 4; i++) {
        int dd = lane + 32 * i;
        float t  = (kp[dd] + qp[dd]) * ewp[dd];
        float ss = (t >= 0.f) ? sqrtf(t) : -sqrtf(-t);   // signed sqrt
        ss = fmaxf(ss + ewp[128 + dd], 0.f);
        vals[i] = ss;
        lg = fmaf(ss, aw[h * DH + dd], lg);
    }
    if (e_out) {
        float* op = e_out + (long long)e * DIM + h * DH;
        #pragma unroll
        for (int i = 0; i < 4; i++) op[lane + 32 * i] = vals[i];
    }
    #pragma unroll
    for (int off = 16; off; off >>= 1) lg += __shfl_xor_sync(0xffffffffu, lg, off);
    if (lane == 0) g_logits[e * NH + h] = lg;
}

__global__ void k_initmz() {
    int i = blockIdx.x * blockDim.x + threadIdx.x;
    if (i < NN * NH) { g_m[i] = __int_as_float(0xff800000); g_z[i] = 0.f; }
}

__device__ __forceinline__ void atomicMaxF(float* addr, float val) {
    int* ia = (int*)addr;
    int old = *ia;
    while (__int_as_float(old) < val) {
        int assumed = old;
        old = atomicCAS(ia, assumed, __float_as_int(val));
        if (old == assumed) break;
    }
}

__global__ void k_max(const int* __restrict__ dst) {
    int i = blockIdx.x * blockDim.x + threadIdx.x;
    if (i >= ET * NH) return;
    int e = i >> 2, h = i & 3;
    atomicMaxF(&g_m[dst[e] * NH + h], g_logits[i]);
}

__global__ void k_expsum(const int* __restrict__ dst) {
    int i = blockIdx.x * blockDim.x + threadIdx.x;
    if (i >= ET * NH) return;
    int e = i >> 2, h = i & 3;
    float wv = expf(g_logits[i] - g_m[dst[e] * NH + h]);
    g_logits[i] = wv;
    atomicAdd(&g_z[dst[e] * NH + h], wv);
}

__global__ void k_msg(const float* __restrict__ Vb, const int* __restrict__ src,
                      const int* __restrict__ dst, float* __restrict__ xout) {
    int w = (blockIdx.x * blockDim.x + threadIdx.x) >> 5;
    int lane = threadIdx.x & 31;
    if (w >= ET * NH) return;
    int e = w >> 2, h = w & 3;
    int sn = src[e], dn = dst[e];
    float alpha = g_logits[e * NH + h] / (g_z[dn * NH + h] + 1e-16f);
    const float* vp = Vb + (long long)sn * DIM + h * DH;
    float* op = xout + (long long)dn * DIM + h * DH;
    #pragma unroll
    for (int i = 0; i < 4; i++) {
        int dd = lane + 32 * i;
        atomicAdd(&op[dd], vp[dd] * alpha);
    }
}

// ---------------- host orchestration ---------------------------------------
extern "C" void kernel_launch(void* const* d_in, const int* in_sizes, int n_in,
                              void* d_out, int out_size) {
    const float* query   = (const float*)d_in[0];
    const int*   ei      = (const int*)  d_in[1];
    const int*   mapping = (const int*)  d_in[2];
    const float* emb     = (const float*)d_in[3];
    // d_in[4] = batch (unused)
    const float* wn_w1 = (const float*)d_in[5];
    const float* wn_b1 = (const float*)d_in[6];
    const float* wn_w2 = (const float*)d_in[7];
    const float* wn_b2 = (const float*)d_in[8];
    const float* wp_w1 = (const float*)d_in[9];
    const float* wp_b1 = (const float*)d_in[10];
    const float* wp_w2 = (const float*)d_in[11];
    const float* wp_b2 = (const float*)d_in[12];
    const float* WQ    = (const float*)d_in[13];
    const float* WK    = (const float*)d_in[14];
    const float* WV    = (const float*)d_in[15];
    const float* WE    = (const float*)d_in[16];
    const float* bE    = (const float*)d_in[17];
    const float* Aw    = (const float*)d_in[18];
    float* out = (float*)d_out;

    float *node_raw, *node_pos, *x, *xn, *Qb, *Kb, *Vb, *eA, *eB, *Ew1, *Ew2;
    cudaGetSymbolAddress((void**)&node_raw, g_node_raw);
    cudaGetSymbolAddress((void**)&node_pos, g_node_pos);
    cudaGetSymbolAddress((void**)&x,   g_x);
    cudaGetSymbolAddress((void**)&xn,  g_xn);
    cudaGetSymbolAddress((void**)&Qb,  g_Q);
    cudaGetSymbolAddress((void**)&Kb,  g_K);
    cudaGetSymbolAddress((void**)&Vb,  g_V);
    cudaGetSymbolAddress((void**)&eA,  g_eA);
    cudaGetSymbolAddress((void**)&eB,  g_eB);
    cudaGetSymbolAddress((void**)&Ew1, g_Ew1);
    cudaGetSymbolAddress((void**)&Ew2, g_Ew2);

    const int* srcp = ei;
    const int* dstp = ei + ET;
    const int T = 256;

    // ---- precompute (position-invariant) ----
    kzero<<<(NN * 8 + T - 1) / T, T>>>(node_raw, NN * 8);
    k_selfloop<<<(ET + T - 1) / T, T>>>(ei, emb);
    k_mlp1<<<(NN * DIM) / T, T>>>(node_raw, wn_w1, wn_b1, x, NN);
    sgemm<<<dim3(DIM / 128, NN / 128), T>>>(x, wn_w2, wn_b2, node_pos, NN, DIM, DIM);
    k_mlp1<<<(ET * DIM) / T, T>>>(emb, wp_w1, wp_b1, eA, ET);
    sgemm<<<dim3(DIM / 128, ET / 128), T>>>(eA, wp_w2, wp_b2, eB, ET, DIM, DIM);
    sgemm<<<dim3((2 * DIM) / 128, ET / 128), T>>>(eB, WE, bE, Ew1, ET, 2 * DIM, DIM);

    const int edgeWarpBlocks = (ET * NH * 32) / T;
    const int ehBlocks = (ET * NH) / T;

    for (int s = 0; s < SQ; s++) {
        k_add<<<(NN * DIM) / T, T>>>(query, node_pos, x, s);
        float* xin = x;
        float* xout = xn;
        for (int l = 0; l < 2; l++) {
            const float* EwEb;
            if (l == 0) {
                EwEb = Ew1;
            } else {
                sgemm<<<dim3((2 * DIM) / 128, ET / 128), T>>>(
                    eA, WE + (long long)DIM * 2 * DIM, bE + 2 * DIM, Ew2, ET, 2 * DIM, DIM);
                EwEb = Ew2;
            }
            const long long wo = (long long)l * DIM * DIM;
            sgemm<<<dim3(DIM / 128, NN / 128), T>>>(xin, WQ + wo, nullptr, Qb, NN, DIM, DIM);
            sgemm<<<dim3(DIM / 128, NN / 128), T>>>(xin, WK + wo, nullptr, Kb, NN, DIM, DIM);
            sgemm<<<dim3(DIM / 128, NN / 128), T>>>(xin, WV + wo, nullptr, Vb, NN, DIM, DIM);

            k_edge<<<edgeWarpBlocks, T>>>(Qb, Kb, srcp, dstp, EwEb, Aw + l * DIM,
                                          (l == 0) ? eA : (float*)nullptr);
            k_initmz<<<(NN * NH + T - 1) / T, T>>>();
            k_max<<<ehBlocks, T>>>(dstp);
            k_expsum<<<ehBlocks, T>>>(dstp);
            kzero<<<(NN * DIM) / T, T>>>(xout, NN * DIM);
            k_msg<<<edgeWarpBlocks, T>>>(Vb, srcp, dstp, xout);
            float* tmp = xin; xin = xout; xout = tmp;
        }
        k_gather<<<(BOUT * DIM + T - 1) / T, T>>>(xin, mapping, out, s);
    }
}

// round 2
// speedup vs baseline: 2.0932x; 2.0932x over previous
#include <cuda_runtime.h>
#include <math.h>
#include <stdint.h>

#define NN   8192
#define SQ   4
#define DIM  512
#define NH   4
#define DH   128
#define ET   73728
#define BOUT 128

// ---------------- scratch (device globals; no runtime alloc allowed) -------
__device__ float g_node_raw[NN * 8];
__device__ float g_node_pos[NN * DIM];
__device__ float g_X   [SQ * NN * DIM];
__device__ float g_Xout[SQ * NN * DIM];
__device__ float g_QKV [(size_t)SQ * NN * 3 * DIM];
__device__ float g_eh  [(size_t)ET * DIM];          // edge MLP hidden
__device__ float g_e0  [(size_t)ET * DIM];          // e0 (position invariant)
__device__ float g_e1  [(size_t)SQ * ET * DIM];     // layer-0 e_out, all positions
__device__ float g_Ew1 [(size_t)ET * 2 * DIM];      // layer-0 Ew/Eb (pos-invariant)
__device__ float g_Ew2 [(size_t)SQ * ET * 2 * DIM]; // layer-1 Ew/Eb (per position)
__device__ float g_logits[SQ * ET * NH];
__device__ float g_m[SQ * NN * NH];
__device__ float g_z[SQ * NN * NH];
__device__ float g_Wpack[2 * DIM * 3 * DIM];        // [layer][K=512][1536]

// ---------------- small utility kernels ------------------------------------
__global__ void kzero(float* __restrict__ p, size_t n) {
    size_t i = (size_t)blockIdx.x * blockDim.x + threadIdx.x;
    if (i < n) p[i] = 0.f;
}

__global__ void k_selfloop(const int* __restrict__ ei, const float* __restrict__ emb) {
    int e = blockIdx.x * blockDim.x + threadIdx.x;
    if (e >= ET) return;
    int s = ei[e], d = ei[ET + e];
    if (s == d) {
        #pragma unroll
        for (int r = 0; r < 8; r++)
            atomicAdd(&g_node_raw[s * 8 + r], emb[e * 8 + r]);
    }
}

// out[n,j] = relu( sum_r in[n,r]*w1[r,j] + b1[j] ), in is rows x 8
__global__ void k_mlp1(const float* __restrict__ in, const float* __restrict__ w1,
                       const float* __restrict__ b1, float* __restrict__ out, int rows) {
    long long idx = (long long)blockIdx.x * blockDim.x + threadIdx.x;
    if (idx >= (long long)rows * DIM) return;
    int n = (int)(idx >> 9), j = (int)(idx & 511);
    const float* ip = in + (long long)n * 8;
    float acc = b1[j];
    #pragma unroll
    for (int r = 0; r < 8; r++) acc = fmaf(ip[r], w1[r * DIM + j], acc);
    out[idx] = fmaxf(acc, 0.f);
}

// X[s][n][j] = query[n][s][j] + node_pos[n][j]   (all 4 positions)
__global__ void k_add(const float* __restrict__ query, const float* __restrict__ npos,
                      float* __restrict__ X) {
    size_t idx = (size_t)blockIdx.x * blockDim.x + threadIdx.x;
    if (idx >= (size_t)SQ * NN * DIM) return;
    int j = (int)(idx & 511);
    int n = (int)((idx >> 9) % NN);
    int s = (int)(idx / ((size_t)NN * DIM));
    X[idx] = query[(size_t)n * SQ * DIM + (size_t)s * DIM + j] + npos[(size_t)n * DIM + j];
}

__global__ void k_gather(const float* __restrict__ X, const int* __restrict__ mapping,
                         float* __restrict__ out) {
    int idx = blockIdx.x * blockDim.x + threadIdx.x;
    if (idx >= BOUT * SQ * DIM) return;
    int j = idx & 511;
    int s = (idx >> 9) & 3;
    int b = idx >> 11;
    out[idx] = X[((size_t)s * NN + mapping[b]) * DIM + j];
}

// pack WQ/WK/WV -> [layer][512][1536]
__global__ void k_packw(const float* __restrict__ WQ, const float* __restrict__ WK,
                        const float* __restrict__ WV) {
    int idx = blockIdx.x * blockDim.x + threadIdx.x;
    if (idx >= 2 * DIM * 3 * DIM) return;
    int j = idx % (3 * DIM);
    int k = (idx / (3 * DIM)) % DIM;
    int l = idx / (3 * DIM * DIM);
    float v;
    if (j < DIM)            v = WQ[(size_t)l * DIM * DIM + k * DIM + j];
    else if (j < 2 * DIM)   v = WK[(size_t)l * DIM * DIM + k * DIM + (j - DIM)];
    else                    v = WV[(size_t)l * DIM * DIM + k * DIM + (j - 2 * DIM)];
    g_Wpack[idx] = v;
}

// ---------------- TF32 tensor-core GEMM ------------------------------------
// C[M,N] = A[M,K] @ B[K,N] (+bias), row-major. M,N mult of 128, K mult of 16.
__device__ __forceinline__ uint32_t f2tf(float x) {
    uint32_t u; asm("cvt.rna.tf32.f32 %0, %1;" : "=r"(u) : "f"(x)); return u;
}
__device__ __forceinline__ void mma_tf32(float& c0, float& c1, float& c2, float& c3,
                                         uint32_t a0, uint32_t a1, uint32_t a2, uint32_t a3,
                                         uint32_t b0, uint32_t b1) {
    asm volatile("mma.sync.aligned.m16n8k8.row.col.f32.tf32.tf32.f32 "
                 "{%0,%1,%2,%3}, {%4,%5,%6,%7}, {%8,%9}, {%0,%1,%2,%3};\n"
                 : "+f"(c0), "+f"(c1), "+f"(c2), "+f"(c3)
                 : "r"(a0), "r"(a1), "r"(a2), "r"(a3), "r"(b0), "r"(b1));
}

#define SPAD 4
__global__ void __launch_bounds__(256, 2)
gemm_tf32(const float* __restrict__ A, const float* __restrict__ B,
          const float* __restrict__ bias, float* __restrict__ C,
          int M, int N, int K) {
    __shared__ uint32_t As[2][16][128 + SPAD];   // [buf][k][m]
    __shared__ uint32_t Bs[2][16][128 + SPAD];   // [buf][k][n]

    const int tid  = threadIdx.x;
    const int lane = tid & 31;
    const int warp = tid >> 5;
    const int wm = warp & 1;      // 2 warps along M
    const int wn = warp >> 1;     // 4 warps along N
    const int tg = lane >> 2;
    const int tc = lane & 3;

    const long long bRow = (long long)blockIdx.y * 128;
    const long long bCol = (long long)blockIdx.x * 128;

    const int ar = tid >> 2;            // 0..63
    const int ac = (tid & 3) * 4;       // 0,4,8,12
    const int bk = tid >> 5;            // 0..7
    const int bn = (tid & 31) * 4;

    const float* Ag0 = A + (bRow + ar)      * (long long)K + ac;
    const float* Ag1 = A + (bRow + ar + 64) * (long long)K + ac;
    const float* Bg0 = B + (long long)bk       * N + bCol + bn;
    const float* Bg1 = B + (long long)(bk + 8) * N + bCol + bn;

    float acc[4][4][4];
    #pragma unroll
    for (int mt = 0; mt < 4; mt++)
        #pragma unroll
        for (int nt = 0; nt < 4; nt++)
            #pragma unroll
            for (int q = 0; q < 4; q++) acc[mt][nt][q] = 0.f;

    const int KT = K >> 4;
    float4 ra0, ra1, rb0, rb1;

    ra0 = *(const float4*)(Ag0);
    ra1 = *(const float4*)(Ag1);
    rb0 = *(const float4*)(Bg0);
    rb1 = *(const float4*)(Bg1);

    // store tile 0 into buf 0
    {
        As[0][ac + 0][ar] = f2tf(ra0.x); As[0][ac + 1][ar] = f2tf(ra0.y);
        As[0][ac + 2][ar] = f2tf(ra0.z); As[0][ac + 3][ar] = f2tf(ra0.w);
        As[0][ac + 0][ar + 64] = f2tf(ra1.x); As[0][ac + 1][ar + 64] = f2tf(ra1.y);
        As[0][ac + 2][ar + 64] = f2tf(ra1.z); As[0][ac + 3][ar + 64] = f2tf(ra1.w);
        uint4 u0 = make_uint4(f2tf(rb0.x), f2tf(rb0.y), f2tf(rb0.z), f2tf(rb0.w));
        uint4 u1 = make_uint4(f2tf(rb1.x), f2tf(rb1.y), f2tf(rb1.z), f2tf(rb1.w));
        *(uint4*)&Bs[0][bk][bn]     = u0;
        *(uint4*)&Bs[0][bk + 8][bn] = u1;
    }
    __syncthreads();

    for (int kt = 0; kt < KT; kt++) {
        const int cur = kt & 1;
        if (kt + 1 < KT) {
            const int ko = (kt + 1) * 16;
            ra0 = *(const float4*)(Ag0 + ko);
            ra1 = *(const float4*)(Ag1 + ko);
            rb0 = *(const float4*)(Bg0 + (long long)ko * N);
            rb1 = *(const float4*)(Bg1 + (long long)ko * N);
        }
        #pragma unroll
        for (int kk = 0; kk < 16; kk += 8) {
            uint32_t af[4][4], bf[4][2];
            #pragma unroll
            for (int mt = 0; mt < 4; mt++) {
                int row = wm * 64 + mt * 16 + tg;
                af[mt][0] = As[cur][kk + tc][row];
                af[mt][1] = As[cur][kk + tc][row + 8];
                af[mt][2] = As[cur][kk + tc + 4][row];
                af[mt][3] = As[cur][kk + tc + 4][row + 8];
            }
            #pragma unroll
            for (int nt = 0; nt < 4; nt++) {
                int col = wn * 32 + nt * 8 + tg;
                bf[nt][0] = Bs[cur][kk + tc][col];
                bf[nt][1] = Bs[cur][kk + tc + 4][col];
            }
            #pragma unroll
            for (int mt = 0; mt < 4; mt++)
                #pragma unroll
                for (int nt = 0; nt < 4; nt++)
                    mma_tf32(acc[mt][nt][0], acc[mt][nt][1], acc[mt][nt][2], acc[mt][nt][3],
                             af[mt][0], af[mt][1], af[mt][2], af[mt][3],
                             bf[nt][0], bf[nt][1]);
        }
        if (kt + 1 < KT) {
            const int nb = (kt + 1) & 1;
            As[nb][ac + 0][ar] = f2tf(ra0.x); As[nb][ac + 1][ar] = f2tf(ra0.y);
            As[nb][ac + 2][ar] = f2tf(ra0.z); As[nb][ac + 3][ar] = f2tf(ra0.w);
            As[nb][ac + 0][ar + 64] = f2tf(ra1.x); As[nb][ac + 1][ar + 64] = f2tf(ra1.y);
            As[nb][ac + 2][ar + 64] = f2tf(ra1.z); As[nb][ac + 3][ar + 64] = f2tf(ra1.w);
            uint4 u0 = make_uint4(f2tf(rb0.x), f2tf(rb0.y), f2tf(rb0.z), f2tf(rb0.w));
            uint4 u1 = make_uint4(f2tf(rb1.x), f2tf(rb1.y), f2tf(rb1.z), f2tf(rb1.w));
            *(uint4*)&Bs[nb][bk][bn]     = u0;
            *(uint4*)&Bs[nb][bk + 8][bn] = u1;
        }
        __syncthreads();
    }

    // epilogue
    #pragma unroll
    for (int mt = 0; mt < 4; mt++) {
        #pragma unroll
        for (int nt = 0; nt < 4; nt++) {
            long long row0 = bRow + wm * 64 + mt * 16 + tg;
            long long col  = bCol + wn * 32 + nt * 8 + tc * 2;
            float b0 = 0.f, b1 = 0.f;
            if (bias) { b0 = bias[col]; b1 = bias[col + 1]; }
            float2 v0 = make_float2(acc[mt][nt][0] + b0, acc[mt][nt][1] + b1);
            float2 v1 = make_float2(acc[mt][nt][2] + b0, acc[mt][nt][3] + b1);
            *(float2*)(C + row0 * N + col)       = v0;
            *(float2*)(C + (row0 + 8) * N + col) = v1;
        }
    }
}

// ---------------- edge attention (batched over positions) ------------------
// warp per (s, e, h)
__global__ void k_edge(const float* __restrict__ QKV,
                       const int* __restrict__ src, const int* __restrict__ dst,
                       const float* __restrict__ EwEb, int sStride,
                       const float* __restrict__ aw, float* __restrict__ e_out) {
    long long w = ((long long)blockIdx.x * blockDim.x + threadIdx.x) >> 5;
    int lane = threadIdx.x & 31;
    if (w >= (long long)SQ * ET * NH) return;
    int s = (int)(w / (ET * NH));
    int r = (int)(w % (ET * NH));
    int e = r >> 2, h = r & 3;
    int sn = src[e], dn = dst[e];
    const float* qp  = QKV + ((size_t)s * NN + dn) * (3 * DIM) + h * DH;            // Q of dst
    const float* kp  = QKV + ((size_t)s * NN + sn) * (3 * DIM) + DIM + h * DH;      // K of src
    const float* ewp = EwEb + ((size_t)s * sStride + e) * (2 * DIM) + h * 256;
    float lg = 0.f;
    float vals[4];
    #pragma unroll
    for (int i = 0; i < 4; i++) {
        int dd = lane + 32 * i;
        float t  = (kp[dd] + qp[dd]) * ewp[dd];
        float ss = (t >= 0.f) ? sqrtf(t) : -sqrtf(-t);   // signed sqrt
        ss = fmaxf(ss + ewp[128 + dd], 0.f);
        vals[i] = ss;
        lg = fmaf(ss, aw[h * DH + dd], lg);
    }
    if (e_out) {
        float* op = e_out + ((size_t)s * ET + e) * DIM + h * DH;
        #pragma unroll
        for (int i = 0; i < 4; i++) op[lane + 32 * i] = vals[i];
    }
    #pragma unroll
    for (int off = 16; off; off >>= 1) lg += __shfl_xor_sync(0xffffffffu, lg, off);
    if (lane == 0) g_logits[(size_t)s * ET * NH + e * NH + h] = lg;
}

__global__ void k_initmz() {
    int i = blockIdx.x * blockDim.x + threadIdx.x;
    if (i < SQ * NN * NH) { g_m[i] = __int_as_float(0xff800000); g_z[i] = 0.f; }
}

__device__ __forceinline__ void atomicMaxF(float* addr, float val) {
    int* ia = (int*)addr;
    int old = *ia;
    while (__int_as_float(old) < val) {
        int assumed = old;
        old = atomicCAS(ia, assumed, __float_as_int(val));
        if (old == assumed) break;
    }
}

__global__ void k_max(const int* __restrict__ dst) {
    int i = blockIdx.x * blockDim.x + threadIdx.x;
    if (i >= SQ * ET * NH) return;
    int s = i / (ET * NH);
    int r = i % (ET * NH);
    int e = r >> 2, h = r & 3;
    atomicMaxF(&g_m[(s * NN + dst[e]) * NH + h], g_logits[i]);
}

__global__ void k_expsum(const int* __restrict__ dst) {
    int i = blockIdx.x * blockDim.x + threadIdx.x;
    if (i >= SQ * ET * NH) return;
    int s = i / (ET * NH);
    int r = i % (ET * NH);
    int e = r >> 2, h = r & 3;
    float wv = expf(g_logits[i] - g_m[(s * NN + dst[e]) * NH + h]);
    g_logits[i] = wv;
    atomicAdd(&g_z[(s * NN + dst[e]) * NH + h], wv);
}

__global__ void k_msg(const float* __restrict__ QKV, const int* __restrict__ src,
                      const int* __restrict__ dst, float* __restrict__ xout) {
    long long w = ((long long)blockIdx.x * blockDim.x + threadIdx.x) >> 5;
    int lane = threadIdx.x & 31;
    if (w >= (long long)SQ * ET * NH) return;
    int s = (int)(w / (ET * NH));
    int r = (int)(w % (ET * NH));
    int e = r >> 2, h = r & 3;
    int sn = src[e], dn = dst[e];
    float alpha = g_logits[(size_t)s * ET * NH + e * NH + h] /
                  (g_z[(s * NN + dn) * NH + h] + 1e-16f);
    const float* vp = QKV + ((size_t)s * NN + sn) * (3 * DIM) + 2 * DIM + h * DH;  // V of src
    float* op = xout + ((size_t)s * NN + dn) * DIM + h * DH;
    #pragma unroll
    for (int i = 0; i < 4; i++) {
        int dd = lane + 32 * i;
        atomicAdd(&op[dd], vp[dd] * alpha);
    }
}

// ---------------- host orchestration ---------------------------------------
extern "C" void kernel_launch(void* const* d_in, const int* in_sizes, int n_in,
                              void* d_out, int out_size) {
    const float* query   = (const float*)d_in[0];
    const int*   ei      = (const int*)  d_in[1];
    const int*   mapping = (const int*)  d_in[2];
    const float* emb     = (const float*)d_in[3];
    // d_in[4] = batch (unused)
    const float* wn_w1 = (const float*)d_in[5];
    const float* wn_b1 = (const float*)d_in[6];
    const float* wn_w2 = (const float*)d_in[7];
    const float* wn_b2 = (const float*)d_in[8];
    const float* wp_w1 = (const float*)d_in[9];
    const float* wp_b1 = (const float*)d_in[10];
    const float* wp_w2 = (const float*)d_in[11];
    const float* wp_b2 = (const float*)d_in[12];
    const float* WQ    = (const float*)d_in[13];
    const float* WK    = (const float*)d_in[14];
    const float* WV    = (const float*)d_in[15];
    const float* WE    = (const float*)d_in[16];
    const float* bE    = (const float*)d_in[17];
    const float* Aw    = (const float*)d_in[18];
    float* out = (float*)d_out;

    float *node_raw, *node_pos, *X, *Xout, *QKV, *eh, *e0, *e1, *Ew1, *Ew2, *Wpack;
    cudaGetSymbolAddress((void**)&node_raw, g_node_raw);
    cudaGetSymbolAddress((void**)&node_pos, g_node_pos);
    cudaGetSymbolAddress((void**)&X,    g_X);
    cudaGetSymbolAddress((void**)&Xout, g_Xout);
    cudaGetSymbolAddress((void**)&QKV,  g_QKV);
    cudaGetSymbolAddress((void**)&eh,   g_eh);
    cudaGetSymbolAddress((void**)&e0,   g_e0);
    cudaGetSymbolAddress((void**)&e1,   g_e1);
    cudaGetSymbolAddress((void**)&Ew1,  g_Ew1);
    cudaGetSymbolAddress((void**)&Ew2,  g_Ew2);
    cudaGetSymbolAddress((void**)&Wpack, g_Wpack);

    const int* srcp = ei;
    const int* dstp = ei + ET;
    const int T = 256;

    // ---- position-invariant precompute ----
    kzero<<<(NN * 8 + T - 1) / T, T>>>(node_raw, NN * 8);
    k_selfloop<<<(ET + T - 1) / T, T>>>(ei, emb);
    k_mlp1<<<(NN * DIM) / T, T>>>(node_raw, wn_w1, wn_b1, X, NN);   // reuse X as tmp
    gemm_tf32<<<dim3(DIM / 128, NN / 128), T>>>(X, wn_w2, wn_b2, node_pos, NN, DIM, DIM);
    k_mlp1<<<(ET * DIM) / T, T>>>(emb, wp_w1, wp_b1, eh, ET);
    gemm_tf32<<<dim3(DIM / 128, ET / 128), T>>>(eh, wp_w2, wp_b2, e0, ET, DIM, DIM);
    gemm_tf32<<<dim3((2 * DIM) / 128, ET / 128), T>>>(e0, WE, bE, Ew1, ET, 2 * DIM, DIM);
    k_packw<<<(2 * DIM * 3 * DIM) / T, T>>>(WQ, WK, WV);

    // ---- batched positions ----
    k_add<<<(SQ * NN * DIM) / T, T>>>(query, node_pos, X);

    const long long edgeWarps = (long long)SQ * ET * NH;
    const int edgeWarpBlocks = (int)((edgeWarps * 32) / T);
    const int ehBlocks = (int)(edgeWarps / T);

    float* xin = X;
    float* xout = Xout;
    for (int l = 0; l < 2; l++) {
        const float* EwEb;
        int sStride;
        if (l == 0) { EwEb = Ew1; sStride = 0; }
        else {
            gemm_tf32<<<dim3((2 * DIM) / 128, (SQ * ET) / 128), T>>>(
                e1, WE + (size_t)DIM * 2 * DIM, bE + 2 * DIM, Ew2, SQ * ET, 2 * DIM, DIM);
            EwEb = Ew2; sStride = ET;
        }
        gemm_tf32<<<dim3((3 * DIM) / 128, (SQ * NN) / 128), T>>>(
            xin, Wpack + (size_t)l * DIM * 3 * DIM, nullptr, QKV, SQ * NN, 3 * DIM, DIM);

        k_edge<<<edgeWarpBlocks, T>>>(QKV, srcp, dstp, EwEb, sStride, Aw + l * DIM,
                                      (l == 0) ? e1 : (float*)nullptr);
        k_initmz<<<(SQ * NN * NH + T - 1) / T, T>>>();
        k_max<<<ehBlocks, T>>>(dstp);
        k_expsum<<<ehBlocks, T>>>(dstp);
        kzero<<<((size_t)SQ * NN * DIM + T - 1) / T, T>>>(xout, (size_t)SQ * NN * DIM);
        k_msg<<<edgeWarpBlocks, T>>>(QKV, srcp, dstp, xout);
        float* tmp = xin; xin = xout; xout = tmp;
    }
    k_gather<<<(BOUT * SQ * DIM) / T, T>>>(xin, mapping, out);
}

// round 3
// speedup vs baseline: 2.6933x; 1.2867x over previous
#include <cuda_runtime.h>
#include <math.h>
#include <stdint.h>

#define NN   8192
#define SQ   4
#define DIM  512
#define NH   4
#define DH   128
#define ET   73728
#define BOUT 128

// ---------------- scratch (device globals; no runtime alloc allowed) -------
__device__ float g_node_raw[NN * 8];
__device__ float g_node_pos[NN * DIM];
__device__ float g_X   [SQ * NN * DIM];
__device__ float g_Xout[SQ * NN * DIM];
__device__ float g_QKV [(size_t)SQ * NN * 3 * DIM];
__device__ float g_eh  [(size_t)ET * DIM];          // edge MLP hidden (tf32-rounded)
__device__ float g_e0  [(size_t)ET * DIM];          // e0 (tf32-rounded)
__device__ float g_e1  [(size_t)SQ * ET * DIM];     // layer-0 e_out (tf32-rounded)
__device__ float g_Ew1 [(size_t)ET * 2 * DIM];      // layer-0 Ew/Eb
__device__ float g_Ew2 [(size_t)SQ * ET * 2 * DIM]; // layer-1 Ew/Eb
__device__ float g_logits[SQ * ET * NH];
__device__ float g_m[SQ * NN * NH];
__device__ float g_z[SQ * NN * NH];
__device__ float g_Wpack[2 * DIM * 3 * DIM];        // rounded fused QKV weights
__device__ float g_wn2r[DIM * DIM];
__device__ float g_wp2r[DIM * DIM];
__device__ float g_WEr[2 * DIM * 2 * DIM];

// ---------------- tf32 helpers ----------------------------------------------
__device__ __forceinline__ uint32_t f2tf(float x) {
    uint32_t u; asm("cvt.rna.tf32.f32 %0, %1;" : "=r"(u) : "f"(x)); return u;
}
__device__ __forceinline__ float f2tf_f(float x) { return __uint_as_float(f2tf(x)); }

// ---------------- small utility kernels ------------------------------------
__global__ void kzero(float* __restrict__ p, size_t n) {
    size_t i = (size_t)blockIdx.x * blockDim.x + threadIdx.x;
    if (i < n) p[i] = 0.f;
}

__global__ void k_round(float* __restrict__ p, size_t n) {
    size_t i = (size_t)blockIdx.x * blockDim.x + threadIdx.x;
    if (i < n) p[i] = f2tf_f(p[i]);
}

__global__ void k_roundcopy(const float* __restrict__ s, float* __restrict__ d, size_t n) {
    size_t i = (size_t)blockIdx.x * blockDim.x + threadIdx.x;
    if (i < n) d[i] = f2tf_f(s[i]);
}

__global__ void k_selfloop(const int* __restrict__ ei, const float* __restrict__ emb) {
    int e = blockIdx.x * blockDim.x + threadIdx.x;
    if (e >= ET) return;
    int s = ei[e], d = ei[ET + e];
    if (s == d) {
        #pragma unroll
        for (int r = 0; r < 8; r++)
            atomicAdd(&g_node_raw[s * 8 + r], emb[e * 8 + r]);
    }
}

// out[n,j] = round_tf32( relu( sum_r in[n,r]*w1[r,j] + b1[j] ) )
__global__ void k_mlp1(const float* __restrict__ in, const float* __restrict__ w1,
                       const float* __restrict__ b1, float* __restrict__ out, int rows) {
    long long idx = (long long)blockIdx.x * blockDim.x + threadIdx.x;
    if (idx >= (long long)rows * DIM) return;
    int n = (int)(idx >> 9), j = (int)(idx & 511);
    const float* ip = in + (long long)n * 8;
    float acc = b1[j];
    #pragma unroll
    for (int r = 0; r < 8; r++) acc = fmaf(ip[r], w1[r * DIM + j], acc);
    out[idx] = f2tf_f(fmaxf(acc, 0.f));
}

// X[s][n][j] = round_tf32( query[n][s][j] + node_pos[n][j] )
__global__ void k_add(const float* __restrict__ query, const float* __restrict__ npos,
                      float* __restrict__ X) {
    size_t idx = (size_t)blockIdx.x * blockDim.x + threadIdx.x;
    if (idx >= (size_t)SQ * NN * DIM) return;
    int j = (int)(idx & 511);
    int n = (int)((idx >> 9) % NN);
    int s = (int)(idx / ((size_t)NN * DIM));
    X[idx] = f2tf_f(query[(size_t)n * SQ * DIM + (size_t)s * DIM + j] +
                    npos[(size_t)n * DIM + j]);
}

__global__ void k_gather(const float* __restrict__ X, const int* __restrict__ mapping,
                         float* __restrict__ out) {
    int idx = blockIdx.x * blockDim.x + threadIdx.x;
    if (idx >= BOUT * SQ * DIM) return;
    int j = idx & 511;
    int s = (idx >> 9) & 3;
    int b = idx >> 11;
    out[idx] = X[((size_t)s * NN + mapping[b]) * DIM + j];
}

// pack WQ/WK/WV -> [layer][512][1536], tf32-rounded
__global__ void k_packw(const float* __restrict__ WQ, const float* __restrict__ WK,
                        const float* __restrict__ WV) {
    int idx = blockIdx.x * blockDim.x + threadIdx.x;
    if (idx >= 2 * DIM * 3 * DIM) return;
    int j = idx % (3 * DIM);
    int k = (idx / (3 * DIM)) % DIM;
    int l = idx / (3 * DIM * DIM);
    float v;
    if (j < DIM)            v = WQ[(size_t)l * DIM * DIM + k * DIM + j];
    else if (j < 2 * DIM)   v = WK[(size_t)l * DIM * DIM + k * DIM + (j - DIM)];
    else                    v = WV[(size_t)l * DIM * DIM + k * DIM + (j - 2 * DIM)];
    g_Wpack[idx] = f2tf_f(v);
}

// ---------------- TF32 tensor-core GEMM, cp.async 3-stage pipeline ----------
// C[M,N] = A[M,K] @ B[K,N] (+bias), row-major. A,B must be tf32-rounded fp32.
// M,N multiples of 128; K multiple of 16.
#define BK      16
#define STAGES  3
#define ASTR    20          // padded A row stride (floats): banks (20*tg+tc) all distinct
#define BSTR    136         // padded B row stride: banks (8*tc+tg) all distinct
#define A_ELEMS (128 * ASTR)
#define B_ELEMS (BK * BSTR)
#define GEMM_SMEM ((STAGES * (A_ELEMS + B_ELEMS)) * 4)

__device__ __forceinline__ void cp16(uint32_t dst, const void* src) {
    asm volatile("cp.async.cg.shared.global [%0], [%1], 16;\n" :: "r"(dst), "l"(src));
}
__device__ __forceinline__ void cp_commit() { asm volatile("cp.async.commit_group;\n"); }
__device__ __forceinline__ void cp_wait1()  { asm volatile("cp.async.wait_group 1;\n"); }

__device__ __forceinline__ void mma_tf32(float& c0, float& c1, float& c2, float& c3,
                                         uint32_t a0, uint32_t a1, uint32_t a2, uint32_t a3,
                                         uint32_t b0, uint32_t b1) {
    asm volatile("mma.sync.aligned.m16n8k8.row.col.f32.tf32.tf32.f32 "
                 "{%0,%1,%2,%3}, {%4,%5,%6,%7}, {%8,%9}, {%0,%1,%2,%3};\n"
                 : "+f"(c0), "+f"(c1), "+f"(c2), "+f"(c3)
                 : "r"(a0), "r"(a1), "r"(a2), "r"(a3), "r"(b0), "r"(b1));
}

__global__ void __launch_bounds__(256, 2)
gemm_tf32(const float* __restrict__ A, const float* __restrict__ B,
          const float* __restrict__ bias, float* __restrict__ C,
          int M, int N, int K, int roundC) {
    extern __shared__ float sm[];
    float* Abase = sm;
    float* Bbase = sm + STAGES * A_ELEMS;

    const int tid  = threadIdx.x;
    const int lane = tid & 31;
    const int warp = tid >> 5;
    const int wm = warp & 1;
    const int wn = warp >> 1;
    const int tg = lane >> 2;
    const int tc = lane & 3;

    const long long bRow = (long long)blockIdx.y * 128;
    const long long bCol = (long long)blockIdx.x * 128;

    // cp.async mapping
    const int arow = tid >> 2;             // 0..63 (and +64)
    const int acol = (tid & 3) * 4;        // 0,4,8,12
    const int brw  = tid >> 5;             // 0..7 (and +8)
    const int bcl  = (tid & 31) * 4;

    const float* Ag0 = A + (bRow + arow)      * (long long)K + acol;
    const float* Ag1 = A + (bRow + arow + 64) * (long long)K + acol;
    const float* Bg0 = B + (long long)brw       * N + bCol + bcl;
    const float* Bg1 = B + (long long)(brw + 8) * N + bCol + bcl;

    uint32_t suA = (uint32_t)__cvta_generic_to_shared(Abase);
    uint32_t suB = (uint32_t)__cvta_generic_to_shared(Bbase);
    const uint32_t aD0 = suA + (uint32_t)(arow * ASTR + acol) * 4u;
    const uint32_t aD1 = suA + (uint32_t)((arow + 64) * ASTR + acol) * 4u;
    const uint32_t bD0 = suB + (uint32_t)(brw * BSTR + bcl) * 4u;
    const uint32_t bD1 = suB + (uint32_t)((brw + 8) * BSTR + bcl) * 4u;

    float acc[4][4][4];
    #pragma unroll
    for (int mt = 0; mt < 4; mt++)
        #pragma unroll
        for (int nt = 0; nt < 4; nt++)
            #pragma unroll
            for (int q = 0; q < 4; q++) acc[mt][nt][q] = 0.f;

    const int KT = K / BK;

    // prologue: stages 0 and 1
    #pragma unroll
    for (int s = 0; s < 2; s++) {
        const int ko = s * BK;
        cp16(aD0 + (uint32_t)(s * A_ELEMS * 4), Ag0 + ko);
        cp16(aD1 + (uint32_t)(s * A_ELEMS * 4), Ag1 + ko);
        cp16(bD0 + (uint32_t)(s * B_ELEMS * 4), Bg0 + (long long)ko * N);
        cp16(bD1 + (uint32_t)(s * B_ELEMS * 4), Bg1 + (long long)ko * N);
        cp_commit();
    }

    for (int kt = 0; kt < KT; kt++) {
        cp_wait1();
        __syncthreads();

        if (kt + 2 < KT) {
            const int st = (kt + 2) % STAGES;
            const int ko = (kt + 2) * BK;
            cp16(aD0 + (uint32_t)(st * A_ELEMS * 4), Ag0 + ko);
            cp16(aD1 + (uint32_t)(st * A_ELEMS * 4), Ag1 + ko);
            cp16(bD0 + (uint32_t)(st * B_ELEMS * 4), Bg0 + (long long)ko * N);
            cp16(bD1 + (uint32_t)(st * B_ELEMS * 4), Bg1 + (long long)ko * N);
        }
        cp_commit();

        const float* Ab = Abase + (kt % STAGES) * A_ELEMS;
        const float* Bb = Bbase + (kt % STAGES) * B_ELEMS;

        #pragma unroll
        for (int kk = 0; kk < BK; kk += 8) {
            uint32_t af[4][4], bf[4][2];
            #pragma unroll
            for (int mt = 0; mt < 4; mt++) {
                int row = wm * 64 + mt * 16 + tg;
                af[mt][0] = __float_as_uint(Ab[row * ASTR + kk + tc]);
                af[mt][1] = __float_as_uint(Ab[(row + 8) * ASTR + kk + tc]);
                af[mt][2] = __float_as_uint(Ab[row * ASTR + kk + tc + 4]);
                af[mt][3] = __float_as_uint(Ab[(row + 8) * ASTR + kk + tc + 4]);
            }
            #pragma unroll
            for (int nt = 0; nt < 4; nt++) {
                int col = wn * 32 + nt * 8 + tg;
                bf[nt][0] = __float_as_uint(Bb[(kk + tc) * BSTR + col]);
                bf[nt][1] = __float_as_uint(Bb[(kk + tc + 4) * BSTR + col]);
            }
            #pragma unroll
            for (int mt = 0; mt < 4; mt++)
                #pragma unroll
                for (int nt = 0; nt < 4; nt++)
                    mma_tf32(acc[mt][nt][0], acc[mt][nt][1], acc[mt][nt][2], acc[mt][nt][3],
                             af[mt][0], af[mt][1], af[mt][2], af[mt][3],
                             bf[nt][0], bf[nt][1]);
        }
        __syncthreads();
    }

    // epilogue
    #pragma unroll
    for (int mt = 0; mt < 4; mt++) {
        #pragma unroll
        for (int nt = 0; nt < 4; nt++) {
            long long row0 = bRow + wm * 64 + mt * 16 + tg;
            long long col  = bCol + wn * 32 + nt * 8 + tc * 2;
            float b0 = 0.f, b1 = 0.f;
            if (bias) { b0 = bias[col]; b1 = bias[col + 1]; }
            float2 v0 = make_float2(acc[mt][nt][0] + b0, acc[mt][nt][1] + b1);
            float2 v1 = make_float2(acc[mt][nt][2] + b0, acc[mt][nt][3] + b1);
            if (roundC) {
                v0.x = f2tf_f(v0.x); v0.y = f2tf_f(v0.y);
                v1.x = f2tf_f(v1.x); v1.y = f2tf_f(v1.y);
            }
            *(float2*)(C + row0 * N + col)       = v0;
            *(float2*)(C + (row0 + 8) * N + col) = v1;
        }
    }
}

// ---------------- edge attention (batched over positions) ------------------
__global__ void k_edge(const float* __restrict__ QKV,
                       const int* __restrict__ src, const int* __restrict__ dst,
                       const float* __restrict__ EwEb, int sStride,
                       const float* __restrict__ aw, float* __restrict__ e_out) {
    long long w = ((long long)blockIdx.x * blockDim.x + threadIdx.x) >> 5;
    int lane = threadIdx.x & 31;
    if (w >= (long long)SQ * ET * NH) return;
    int s = (int)(w / (ET * NH));
    int r = (int)(w % (ET * NH));
    int e = r >> 2, h = r & 3;
    int sn = src[e], dn = dst[e];
    const float* qp  = QKV + ((size_t)s * NN + dn) * (3 * DIM) + h * DH;
    const float* kp  = QKV + ((size_t)s * NN + sn) * (3 * DIM) + DIM + h * DH;
    const float* ewp = EwEb + ((size_t)s * sStride + e) * (2 * DIM) + h * 256;
    float lg = 0.f;
    float vals[4];
    #pragma unroll
    for (int i = 0; i < 4; i++) {
        int dd = lane + 32 * i;
        float t  = (kp[dd] + qp[dd]) * ewp[dd];
        float ss = (t >= 0.f) ? sqrtf(t) : -sqrtf(-t);   // signed sqrt
        ss = fmaxf(ss + ewp[128 + dd], 0.f);
        vals[i] = ss;
        lg = fmaf(ss, aw[h * DH + dd], lg);
    }
    if (e_out) {
        float* op = e_out + ((size_t)s * ET + e) * DIM + h * DH;
        #pragma unroll
        for (int i = 0; i < 4; i++) op[lane + 32 * i] = f2tf_f(vals[i]);
    }
    #pragma unroll
    for (int off = 16; off; off >>= 1) lg += __shfl_xor_sync(0xffffffffu, lg, off);
    if (lane == 0) g_logits[(size_t)s * ET * NH + e * NH + h] = lg;
}

__global__ void k_initmz() {
    int i = blockIdx.x * blockDim.x + threadIdx.x;
    if (i < SQ * NN * NH) { g_m[i] = __int_as_float(0xff800000); g_z[i] = 0.f; }
}

__device__ __forceinline__ void atomicMaxF(float* addr, float val) {
    int* ia = (int*)addr;
    int old = *ia;
    while (__int_as_float(old) < val) {
        int assumed = old;
        old = atomicCAS(ia, assumed, __float_as_int(val));
        if (old == assumed) break;
    }
}

__global__ void k_max(const int* __restrict__ dst) {
    int i = blockIdx.x * blockDim.x + threadIdx.x;
    if (i >= SQ * ET * NH) return;
    int s = i / (ET * NH);
    int r = i % (ET * NH);
    int e = r >> 2, h = r & 3;
    atomicMaxF(&g_m[(s * NN + dst[e]) * NH + h], g_logits[i]);
}

__global__ void k_expsum(const int* __restrict__ dst) {
    int i = blockIdx.x * blockDim.x + threadIdx.x;
    if (i >= SQ * ET * NH) return;
    int s = i / (ET * NH);
    int r = i % (ET * NH);
    int e = r >> 2, h = r & 3;
    float wv = expf(g_logits[i] - g_m[(s * NN + dst[e]) * NH + h]);
    g_logits[i] = wv;
    atomicAdd(&g_z[(s * NN + dst[e]) * NH + h], wv);
}

__global__ void k_msg(const float* __restrict__ QKV, const int* __restrict__ src,
                      const int* __restrict__ dst, float* __restrict__ xout) {
    long long w = ((long long)blockIdx.x * blockDim.x + threadIdx.x) >> 5;
    int lane = threadIdx.x & 31;
    if (w >= (long long)SQ * ET * NH) return;
    int s = (int)(w / (ET * NH));
    int r = (int)(w % (ET * NH));
    int e = r >> 2, h = r & 3;
    int sn = src[e], dn = dst[e];
    float alpha = g_logits[(size_t)s * ET * NH + e * NH + h] /
                  (g_z[(s * NN + dn) * NH + h] + 1e-16f);
    const float* vp = QKV + ((size_t)s * NN + sn) * (3 * DIM) + 2 * DIM + h * DH;
    float* op = xout + ((size_t)s * NN + dn) * DIM + h * DH;
    #pragma unroll
    for (int i = 0; i < 4; i++) {
        int dd = lane + 32 * i;
        atomicAdd(&op[dd], vp[dd] * alpha);
    }
}

// ---------------- host orchestration ---------------------------------------
extern "C" void kernel_launch(void* const* d_in, const int* in_sizes, int n_in,
                              void* d_out, int out_size) {
    const float* query   = (const float*)d_in[0];
    const int*   ei      = (const int*)  d_in[1];
    const int*   mapping = (const int*)  d_in[2];
    const float* emb     = (const float*)d_in[3];
    const float* wn_w1 = (const float*)d_in[5];
    const float* wn_b1 = (const float*)d_in[6];
    const float* wn_w2 = (const float*)d_in[7];
    const float* wn_b2 = (const float*)d_in[8];
    const float* wp_w1 = (const float*)d_in[9];
    const float* wp_b1 = (const float*)d_in[10];
    const float* wp_w2 = (const float*)d_in[11];
    const float* wp_b2 = (const float*)d_in[12];
    const float* WQ    = (const float*)d_in[13];
    const float* WK    = (const float*)d_in[14];
    const float* WV    = (const float*)d_in[15];
    const float* WE    = (const float*)d_in[16];
    const float* bE    = (const float*)d_in[17];
    const float* Aw    = (const float*)d_in[18];
    float* out = (float*)d_out;

    float *node_raw, *node_pos, *X, *Xout, *QKV, *eh, *e0, *e1, *Ew1, *Ew2;
    float *Wpack, *wn2r, *wp2r, *WEr;
    cudaGetSymbolAddress((void**)&node_raw, g_node_raw);
    cudaGetSymbolAddress((void**)&node_pos, g_node_pos);
    cudaGetSymbolAddress((void**)&X,    g_X);
    cudaGetSymbolAddress((void**)&Xout, g_Xout);
    cudaGetSymbolAddress((void**)&QKV,  g_QKV);
    cudaGetSymbolAddress((void**)&eh,   g_eh);
    cudaGetSymbolAddress((void**)&e0,   g_e0);
    cudaGetSymbolAddress((void**)&e1,   g_e1);
    cudaGetSymbolAddress((void**)&Ew1,  g_Ew1);
    cudaGetSymbolAddress((void**)&Ew2,  g_Ew2);
    cudaGetSymbolAddress((void**)&Wpack, g_Wpack);
    cudaGetSymbolAddress((void**)&wn2r, g_wn2r);
    cudaGetSymbolAddress((void**)&wp2r, g_wp2r);
    cudaGetSymbolAddress((void**)&WEr,  g_WEr);

    static int smemSet = 0;
    if (!smemSet) {
        cudaFuncSetAttribute(gemm_tf32, cudaFuncAttributeMaxDynamicSharedMemorySize, GEMM_SMEM);
        smemSet = 1;
    }

    const int* srcp = ei;
    const int* dstp = ei + ET;
    const int T = 256;

    // ---- round weights (tiny) ----
    k_roundcopy<<<(DIM * DIM + T - 1) / T, T>>>(wn_w2, wn2r, DIM * DIM);
    k_roundcopy<<<(DIM * DIM + T - 1) / T, T>>>(wp_w2, wp2r, DIM * DIM);
    k_roundcopy<<<(2 * DIM * 2 * DIM + T - 1) / T, T>>>(WE, WEr, 2 * DIM * 2 * DIM);
    k_packw<<<(2 * DIM * 3 * DIM) / T, T>>>(WQ, WK, WV);

    // ---- position-invariant precompute ----
    kzero<<<(NN * 8 + T - 1) / T, T>>>(node_raw, NN * 8);
    k_selfloop<<<(ET + T - 1) / T, T>>>(ei, emb);
    k_mlp1<<<(NN * DIM) / T, T>>>(node_raw, wn_w1, wn_b1, X, NN);   // reuse X as tmp
    gemm_tf32<<<dim3(DIM / 128, NN / 128), T, GEMM_SMEM>>>(X, wn2r, wn_b2, node_pos,
                                                           NN, DIM, DIM, 0);
    k_mlp1<<<(ET * DIM) / T, T>>>(emb, wp_w1, wp_b1, eh, ET);
    gemm_tf32<<<dim3(DIM / 128, ET / 128), T, GEMM_SMEM>>>(eh, wp2r, wp_b2, e0,
                                                           ET, DIM, DIM, 1);
    gemm_tf32<<<dim3((2 * DIM) / 128, ET / 128), T, GEMM_SMEM>>>(e0, WEr, bE, Ew1,
                                                                 ET, 2 * DIM, DIM, 0);

    // ---- batched positions ----
    k_add<<<(SQ * NN * DIM) / T, T>>>(query, node_pos, X);

    const long long edgeWarps = (long long)SQ * ET * NH;
    const int edgeWarpBlocks = (int)((edgeWarps * 32) / T);
    const int ehBlocks = (int)(edgeWarps / T);

    float* xin = X;
    float* xout = Xout;
    for (int l = 0; l < 2; l++) {
        const float* EwEb;
        int sStride;
        if (l == 0) { EwEb = Ew1; sStride = 0; }
        else {
            gemm_tf32<<<dim3((2 * DIM) / 128, (SQ * ET) / 128), T, GEMM_SMEM>>>(
                e1, WEr + (size_t)DIM * 2 * DIM, bE + 2 * DIM, Ew2, SQ * ET, 2 * DIM, DIM, 0);
            EwEb = Ew2; sStride = ET;
        }
        gemm_tf32<<<dim3((3 * DIM) / 128, (SQ * NN) / 128), T, GEMM_SMEM>>>(
            xin, Wpack + (size_t)l * DIM * 3 * DIM, nullptr, QKV, SQ * NN, 3 * DIM, DIM, 0);

        k_edge<<<edgeWarpBlocks, T>>>(QKV, srcp, dstp, EwEb, sStride, Aw + l * DIM,
                                      (l == 0) ? e1 : (float*)nullptr);
        k_initmz<<<(SQ * NN * NH + T - 1) / T, T>>>();
        k_max<<<ehBlocks, T>>>(dstp);
        k_expsum<<<ehBlocks, T>>>(dstp);
        kzero<<<((size_t)SQ * NN * DIM + T - 1) / T, T>>>(xout, (size_t)SQ * NN * DIM);
        k_msg<<<edgeWarpBlocks, T>>>(QKV, srcp, dstp, xout);
        if (l == 0)
            k_round<<<((size_t)SQ * NN * DIM + T - 1) / T, T>>>(xout, (size_t)SQ * NN * DIM);
        float* tmp = xin; xin = xout; xout = tmp;
    }
    k_gather<<<(BOUT * SQ * DIM) / T, T>>>(xin, mapping, out);
}